// round 16
// baseline (speedup 1.0000x reference)
#include <cuda_runtime.h>
#include <cstdint>
#include <math.h>

#define T      1024
#define LRC    0.01f

#define SFQ   1048            // sF row stride (20 front pad + 1024 + 4 tail)
#define NF4   262             // float4 per sF row
#define SW0   8384            // cw region start (floats): 2 rows x 1024
#define RED0  10432           // reduction region start (floats)
#define RSEG  6144            // reduction floats per rsl segment (16*128+16*256)
#define SMEMF 22720           // total dyn smem floats (90,880 B)

// Scratch (device globals — allocation is forbidden)
__device__ float g_part[256];      // per-CTA err-dot partials (rewritten each launch)
__device__ unsigned int g_bar;     // monotonic grid barrier (never reset)

extern __shared__ float smem[];

// ---------------------------------------------------------------------------
// Single fused kernel. grid (32 pair-tiles, 8 rs-octants) = 256 CTAs, 640 thr,
// 2 CTAs/SM (all resident -> spin barrier safe). Each CTA owns 2 rs rows and
// ALL 4 e: cw is computed post-barrier purely from smem (no global re-reads —
// the fix for R13's regression).
//   pre-barrier : cp.async stage 8 Fx rows + 2 w0 rows; err-dot partial;
//                 out-zero / gamma on designated CTAs
//   barrier     : monotonic atomic counter (replay-safe)
//   post-barrier: fixed-order err sums -> cw in smem -> 4 conv rounds (per e)
//                 -> overlay reduce -> atomicAdd out (pre-zeroed)
// ---------------------------------------------------------------------------
__global__ void __launch_bounds__(640, 2)
kfused(const float* __restrict__ Fx, const float* __restrict__ Dis,
       const float* __restrict__ w0, float* __restrict__ out) {
    __shared__ float sP[2];
    __shared__ float sE[4][2];
    __shared__ float sErr[4];
    __shared__ float sDis[4];

    const int tid = threadIdx.x;
    const int b   = blockIdx.x;            // 0..31 pair-tile
    const int rso = blockIdx.y;            // 0..7 rs-octant (2 rs rows)
    const int lin = (rso << 5) + b;        // 0..255

    const float4* fx4 = (const float4*)Fx;
    const float4* w04 = (const float4*)w0;
    const float4 z4 = make_float4(0.f, 0.f, 0.f, 0.f);
    float4* dF = (float4*)smem;

    // ---- Dis prefetch (warp 19, off the critical path) ----
    if (tid >= 608 && tid < 612) sDis[tid - 608] = Dis[(tid - 608) * T + (T - 1)];

    // ---- zero pads for the 8 sF rows: front 5 f4 + tail f4 each ----
    if (tid < 64) {
        const int r = tid >> 3, j = tid & 7;
        if (j < 6) dF[r * NF4 + ((j < 5) ? j : 261)] = z4;
    }

    // ---- cp.async stage: 8 Fx rows (r = e*2+rsl) + 2 w0 rows ----
    for (int idx = tid; idx < 2560; idx += 640) {
        if (idx < 2048) {
            const int r = idx >> 8, c = idx & 255;       // r: e = r>>1, rsl = r&1
            const int gr = (((rso << 1) + (r & 1)) << 2) + (r >> 1);
            const float4* g = fx4 + (gr << 8) + c;
            const unsigned int s =
                (unsigned int)__cvta_generic_to_shared(dF + r * NF4 + 5 + c);
            asm volatile("cp.async.ca.shared.global [%0], [%1], 16;"
                         :: "r"(s), "l"(g) : "memory");
        } else {
            const int j = idx - 2048;                    // 0..511
            const int rsl = j >> 8, c = j & 255;
            const float4* g = w04 + (((rso << 1) + rsl) << 8) + c;
            const unsigned int s = (unsigned int)__cvta_generic_to_shared(
                (float4*)(smem + SW0) + (rsl << 8) + c);
            asm volatile("cp.async.ca.shared.global [%0], [%1], 16;"
                         :: "r"(s), "l"(g) : "memory");
        }
    }
    asm volatile("cp.async.commit_group;" ::: "memory");

    // ---- err-dot partial for task (rs, n-quarter, ee) = decode(lin) ----
    if (tid < 64) {
        const int rs = lin >> 4, q4 = (lin >> 2) & 3, ee = lin & 3;
        const int base = (q4 << 6) + tid;
        const float4 x = fx4[(((rs << 2) + ee) << 8) + base];
        const float4 w = w04[(rs << 8) + base];
        float v = x.x * w.x + x.y * w.y + x.z * w.z + x.w * w.w;
#pragma unroll
        for (int o = 16; o; o >>= 1) v += __shfl_xor_sync(0xffffffffu, v, o);
        if ((tid & 31) == 0) sP[tid >> 5] = v;
    }

    // ---- out zero-init (lin<4) and gamma (lin 4..7) ----
    if (lin < 4) {
        if (tid < 256) ((float4*)out)[(lin << 8) + tid] = z4;
    } else if (lin < 8) {
        if (tid < 256) {
            const int g = ((lin - 4) << 8) + tid;
            out[4096 + g] = __expf((float)(1023 - g) * -1.0005003e-3f);
        }
    }

    asm volatile("cp.async.wait_group 0;" ::: "memory");
    __syncthreads();

    // ---- grid barrier (monotonic, replay-safe) ----
    if (tid == 0) {
        g_part[lin] = sP[0] + sP[1];
        __threadfence();                                 // release
        const unsigned int old = atomicAdd(&g_bar, 1u);
        const unsigned int target = (old & ~255u) + 256u;
        while (*(volatile unsigned int*)&g_bar < target) { }
    }
    __syncthreads();
    __threadfence();                                     // acquire side

    // ---- fixed-order err sums ----
    if (tid < 256) {
        const int eo = tid >> 6, idx = tid & 63;
        const int rs = idx >> 2, q4 = idx & 3;
        float v = g_part[(rs << 4) + (q4 << 2) + eo];
#pragma unroll
        for (int o = 16; o; o >>= 1) v += __shfl_xor_sync(0xffffffffu, v, o);
        if ((tid & 31) == 0) sE[eo][(tid >> 5) & 1] = v;
    }
    __syncthreads();
    if (tid < 4)
        sErr[tid] = sDis[tid] - (sE[tid][0] + sE[tid][1]);
    __syncthreads();

    // ---- cw for this CTA's 2 rs rows, purely from smem ----
    {
        const float er0 = sErr[0], er1 = sErr[1], er2 = sErr[2], er3 = sErr[3];
        for (int idx = tid; idx < 2048; idx += 640) {
            const int rsl = idx >> 10, n = idx & 1023;
            const float f0 = smem[(0 + rsl) * SFQ + 20 + n];
            const float f1 = smem[(2 + rsl) * SFQ + 20 + n];
            const float f2 = smem[(4 + rsl) * SFQ + 20 + n];
            const float f3 = smem[(6 + rsl) * SFQ + 20 + n];
            smem[SW0 + idx] += LRC * (f0 * er0 + f1 * er1 + f2 * er2 + f3 * er3);
        }
    }
    __syncthreads();

    // ---- conv rounds: one per e; proven R14/R15 chunk geometry ----
    const int sub  = (tid >= 320);                  // rsl
    const int tloc = tid - (sub ? 320 : 0);
    const int t0A = b << 4, t0B = (63 - b) << 4;
    const int cA = (b + 1) << 2;                    // 4..128 chunks, tile A
    const int cB = 260 - cA;                        // chunks, tile B
    const bool active = tloc < 260;
    const bool isA = tloc < cA;
    const int t0 = isA ? t0A : t0B;
    const int nb = (isA ? tloc : (tloc - cA)) << 2;
    const int ab = 16 + t0 - nb;

    for (int e = 0; e < 4; e++) {
        float acc[16];
#pragma unroll
        for (int j = 0; j < 16; j++) acc[j] = 0.f;

        if (active) {
            const float4 w = *(const float4*)&smem[SW0 + (sub << 10) + nb];
            const float4* F4 = (const float4*)&smem[((e << 1) + sub) * SFQ + ab];
            float ff[24];
#pragma unroll
            for (int m = 0; m < 6; m++) {
                const float4 v = F4[m];
                ff[4 * m + 0] = v.x; ff[4 * m + 1] = v.y;
                ff[4 * m + 2] = v.z; ff[4 * m + 3] = v.w;
            }
#pragma unroll
            for (int j = 0; j < 16; j++)
                acc[j] += ff[4 + j] * w.x + ff[3 + j] * w.y
                        + ff[2 + j] * w.z + ff[1 + j] * w.w;
        }
        __syncthreads();        // previous round's reduce has finished reading

        float* redA = smem + RED0 + sub * RSEG;     // [16][128]
        float* redB = redA + 2048;                  // [16][256]
        if (active) {
            if (isA) {
#pragma unroll
                for (int j = 0; j < 16; j++) redA[j * 128 + tloc] = acc[j];
            } else {
#pragma unroll
                for (int j = 0; j < 16; j++) redB[j * 256 + (tloc - cA)] = acc[j];
            }
        }
        __syncthreads();

        if (tid < 512) {
            const int row = tid >> 4, k = tid & 15;
            float s = 0.f;
            if (row < 16) {
                for (int c = k; c < cA; c += 16)
                    s += smem[RED0 + row * 128 + c]
                       + smem[RED0 + RSEG + row * 128 + c];
            } else {
                const int r2 = row - 16;
                for (int c = k; c < cB; c += 16)
                    s += smem[RED0 + 2048 + r2 * 256 + c]
                       + smem[RED0 + RSEG + 2048 + r2 * 256 + c];
            }
#pragma unroll
            for (int o = 8; o; o >>= 1) s += __shfl_xor_sync(0xffffffffu, s, o);

            if (k == 0) {
                const int t = (row < 16) ? (t0A + row) : (t0B + row - 16);
                atomicAdd(&out[(t << 2) + e], s);   // 8 rs-octant contributors
            }
        }
    }
}

// ---------------------------------------------------------------------------
extern "C" void kernel_launch(void* const* d_in, const int* in_sizes, int n_in,
                              void* d_out, int out_size) {
    const float* Fx  = (const float*)d_in[0];   // [4,4,4,1024]
    const float* Dis = (const float*)d_in[1];   // [4,1024]
    const float* w0  = (const float*)d_in[2];   // [4,4,1024]
    float* out = (float*)d_out;                 // [1024*4 anti | 1024 gamma]

    const size_t dynBytes = (size_t)SMEMF * sizeof(float);   // 90,880 B
    cudaFuncSetAttribute(kfused, cudaFuncAttributeMaxDynamicSharedMemorySize,
                         (int)dynBytes);
    kfused<<<dim3(32, 8), 640, dynBytes>>>(Fx, Dis, w0, out);
}

// round 17
// speedup vs baseline: 1.4937x; 1.4937x over previous
#include <cuda_runtime.h>
#include <cstdint>
#include <math.h>

#define T      1024
#define LRC    0.01f

// Scratch (device globals — allocation is forbidden)
__device__ float g_cw[16 * T];      // control weights [rs, n]
__device__ float g_epart[32];       // 8 ranks x 4 e partials
__device__ unsigned int g_bar1;     // monotonic 8-CTA barrier (never reset)

// ---------------------------------------------------------------------------
// k1 (8 plain CTAs, 256 thr — NO cluster): fused err + cw + gamma + out-zero.
// Fires the PDL trigger immediately so k2 can start staging Fx in parallel.
// 8-CTA sync via monotonic atomic barrier (replay-safe, R13/R16-proven).
// Fx/w0 register-cached across phases; Dis prefetched to smem.
// ---------------------------------------------------------------------------
__global__ void k1(const float* __restrict__ Fx, const float* __restrict__ Dis,
                   const float* __restrict__ w0, float* __restrict__ out) {
    asm volatile("griddepcontrol.launch_dependents;");

    const int tid  = threadIdx.x;
    const int rank = blockIdx.x;
    const float4* w4  = (const float4*)w0;
    const float4* fx4 = (const float4*)Fx;

    __shared__ float sp[8][4];
    __shared__ float sPart[4];
    __shared__ float serr[4];
    __shared__ float sDis[4];
    __shared__ unsigned int sTarget;

    if (tid < 4) sDis[tid] = Dis[tid * T + (T - 1)];

    // ---- phase A: err-dot partials; cache all operands in registers ----
    float4 wv[2];
    float4 xv[2][4];
    float acc[4] = {0.f, 0.f, 0.f, 0.f};
#pragma unroll
    for (int s = 0; s < 2; s++) {
        const int i4 = rank * 512 + s * 256 + tid;    // float4 index into w0
        wv[s] = w4[i4];
        const int rs = i4 >> 8, n4 = i4 & 255;
#pragma unroll
        for (int e = 0; e < 4; e++) {
            const float4 x = fx4[(rs << 10) + (e << 8) + n4];
            xv[s][e] = x;
            acc[e] += x.x * wv[s].x + x.y * wv[s].y + x.z * wv[s].z + x.w * wv[s].w;
        }
    }
#pragma unroll
    for (int o = 16; o; o >>= 1)
#pragma unroll
        for (int e = 0; e < 4; e++) acc[e] += __shfl_xor_sync(0xffffffffu, acc[e], o);

    if ((tid & 31) == 0)
#pragma unroll
        for (int e = 0; e < 4; e++) sp[tid >> 5][e] = acc[e];
    __syncthreads();
    if (tid < 4) {
        float s = 0.f;
#pragma unroll
        for (int wq = 0; wq < 8; wq++) s += sp[wq][tid];
        sPart[tid] = s;
    }
    __syncthreads();

    // ---- release: tid0 publishes partials, then arrives at the barrier ----
    if (tid == 0) {
#pragma unroll
        for (int e = 0; e < 4; e++) g_epart[rank * 4 + e] = sPart[e];
        __threadfence();
        const unsigned int old = atomicAdd(&g_bar1, 1u);
        sTarget = (old & ~7u) + 8u;
    }

    // ---- barrier gap: zero out[0:4096) + gamma vector (independent work) ----
    {
        const int g = rank * 256 + tid;               // 0..2047
        if (g < 1024) {
            ((float4*)out)[g] = make_float4(0.f, 0.f, 0.f, 0.f);
            out[4096 + g] = __expf((float)(1023 - g) * -1.0005003e-3f);
        }
    }
    __syncthreads();                                  // sTarget visible

    // ---- spin + acquire ----
    if (tid == 0) {
        const unsigned int target = sTarget;
        while (*(volatile unsigned int*)&g_bar1 < target) { }
    }
    __syncthreads();
    __threadfence();

    if (tid < 4) {
        volatile const float* gp = g_epart;
        float s = 0.f;
#pragma unroll
        for (int r = 0; r < 8; r++) s += gp[r * 4 + tid];
        serr[tid] = sDis[tid] - s;
    }
    __syncthreads();
    const float e0 = serr[0], e1 = serr[1], e2 = serr[2], e3 = serr[3];

    // ---- phase B: cw from register-cached operands (no reloads) ----
    float4* cw4 = (float4*)g_cw;
#pragma unroll
    for (int s = 0; s < 2; s++) {
        const int i4 = rank * 512 + s * 256 + tid;
        float4 c = wv[s];
        c.x += LRC * (xv[s][0].x * e0 + xv[s][1].x * e1 + xv[s][2].x * e2 + xv[s][3].x * e3);
        c.y += LRC * (xv[s][0].y * e0 + xv[s][1].y * e1 + xv[s][2].y * e2 + xv[s][3].y * e3);
        c.z += LRC * (xv[s][0].z * e0 + xv[s][1].z * e1 + xv[s][2].z * e2 + xv[s][3].z * e3);
        c.w += LRC * (xv[s][0].w * e0 + xv[s][1].w * e1 + xv[s][2].w * e2 + xv[s][3].w * e3);
        cw4[i4] = c;
    }
}

// ---------------------------------------------------------------------------
// k2 (identical to proven R15): causal correlation. grid (32,4,2) = 256 CTAs,
// 640 thr, 2 CTAs/SM, ONE wave. cp.async staging (division-free), cw via
// __ldg, PDL wait directly before compute. Reduction: overlay -> 32 rows x
// 16 lanes + shuffle -> atomicAdd out (2 contributors -> deterministic).
// ---------------------------------------------------------------------------
#define SFQ   1048            // sF row stride in floats (20 pad + 1024 + 4 tail)
#define NF4   262             // float4 per sF row
#define RSEG  6144            // reduction floats per sub-group (16*128+16*256)

extern __shared__ float smem[];

__global__ void __launch_bounds__(640, 2)
k2(const float* __restrict__ Fx, float* __restrict__ out) {
    const int tid  = threadIdx.x;
    const int b    = blockIdx.x;
    const int e    = blockIdx.y;
    const int half = blockIdx.z;                    // rs-half
    const int sub  = (tid >= 320);                  // qq sub-group
    const int tloc = tid - (sub << 8) - (sub << 6); // tid - sub*320
    const int t0A = b << 4, t0B = (63 - b) << 4;
    const int cA = (b + 1) << 2;                    // 4..128 chunks for tile A
    const int cB = 260 - cA;                        // chunks for tile B
    const bool active = tloc < 260;
    const bool isA = tloc < cA;
    const int t0 = isA ? t0A : t0B;
    const int nb = (isA ? tloc : (tloc - cA)) << 2; // n-chunk base
    const int ab = 16 + t0 - nb;                    // aligned sF read base

    const float4 z4 = make_float4(0.f, 0.f, 0.f, 0.f);
    const float4* fx4 = (const float4*)Fx;
    float4* dF = (float4*)smem;

    // ---- stage this half's 8 Fx rows via cp.async (k1-independent) ----
    if (tid < 64) {
        const int qq = tid >> 3, j = tid & 7;
        if (j < 6) dF[qq * NF4 + ((j < 5) ? j : 261)] = z4;
    }
    for (int idx = tid; idx < 2048; idx += 640) {
        const int qq = idx >> 8, c = idx & 255;
        const float4* g = fx4 + (((((half << 3) + qq) << 2) + e) << 8) + c;
        const unsigned int s =
            (unsigned int)__cvta_generic_to_shared(dF + qq * NF4 + 5 + c);
        asm volatile("cp.async.ca.shared.global [%0], [%1], 16;"
                     :: "r"(s), "l"(g) : "memory");
    }
    asm volatile("cp.async.commit_group;" ::: "memory");
    asm volatile("cp.async.wait_group 0;" ::: "memory");
    __syncthreads();

    // ---- wait for k1 (g_cw + out zero-init), then compute directly ----
    asm volatile("griddepcontrol.wait;" ::: "memory");

    // ---- compute: 4 rs rows per thread; cw straight from L2/L1 via LDG ----
    float acc[16];
#pragma unroll
    for (int j = 0; j < 16; j++) acc[j] = 0.f;

    if (active) {
        const float4* wG = (const float4*)
            (g_cw + (((half << 3) + (sub << 2)) << 10) + nb); // row stride 1024
        const float* fBase = &smem[(sub << 2) * SFQ + ab];
#pragma unroll
        for (int qq = 0; qq < 4; qq++) {
            const float4 w = __ldg(wG + (qq << 8));           // (qq*1024)/4
            const float4* F4 = (const float4*)(fBase + qq * SFQ);
            float ff[24];
#pragma unroll
            for (int m = 0; m < 6; m++) {
                const float4 v = F4[m];
                ff[4 * m + 0] = v.x; ff[4 * m + 1] = v.y;
                ff[4 * m + 2] = v.z; ff[4 * m + 3] = v.w;
            }
#pragma unroll
            for (int j = 0; j < 16; j++)
                acc[j] += ff[4 + j] * w.x + ff[3 + j] * w.y
                        + ff[2 + j] * w.z + ff[1 + j] * w.w;
        }
    }
    __syncthreads();

    // ---- per-chunk partials overlay the staging buffer ----
    float* redA = smem + sub * RSEG;
    float* redB = redA + 16 * 128;
    if (active) {
        if (isA) {
#pragma unroll
            for (int j = 0; j < 16; j++) redA[j * 128 + tloc] = acc[j];
        } else {
#pragma unroll
            for (int j = 0; j < 16; j++) redB[j * 256 + (tloc - cA)] = acc[j];
        }
    }
    __syncthreads();

    // ---- reduce: 32 rows x 16 lanes, shuffle within 16-lane groups ----
    if (tid < 512) {
        const int row = tid >> 4, k = tid & 15;
        float s = 0.f;
        if (row < 16) {
            for (int c = k; c < cA; c += 16)
                s += smem[row * 128 + c] + smem[RSEG + row * 128 + c];
        } else {
            const int r2 = row - 16;
            for (int c = k; c < cB; c += 16)
                s += smem[2048 + r2 * 256 + c] + smem[RSEG + 2048 + r2 * 256 + c];
        }
#pragma unroll
        for (int o = 8; o; o >>= 1) s += __shfl_xor_sync(0xffffffffu, s, o);

        if (k == 0) {
            const int t = (row < 16) ? (t0A + row) : (t0B + row - 16);
            atomicAdd(&out[(t << 2) + e], s);   // 2 contributors: deterministic
        }
    }
}

// ---------------------------------------------------------------------------
extern "C" void kernel_launch(void* const* d_in, const int* in_sizes, int n_in,
                              void* d_out, int out_size) {
    const float* Fx  = (const float*)d_in[0];   // [4,4,4,1024]
    const float* Dis = (const float*)d_in[1];   // [4,1024]
    const float* w0  = (const float*)d_in[2];   // [4,4,1024]
    float* out = (float*)d_out;                 // [1024*4 anti | 1024 gamma]

    k1<<<8, 256>>>(Fx, Dis, w0, out);

    // k2 with programmatic dependent launch (overlaps with k1)
    const size_t dynBytes = (size_t)(2 * RSEG) * sizeof(float);  // 49,152 B
    cudaLaunchConfig_t cfg = {};
    cfg.gridDim = dim3(32, 4, 2);
    cfg.blockDim = dim3(640);
    cfg.dynamicSmemBytes = dynBytes;
    cfg.stream = 0;
    cudaLaunchAttribute attr[1];
    attr[0].id = cudaLaunchAttributeProgrammaticStreamSerialization;
    attr[0].val.programmaticStreamSerializationAllowed = 1;
    cfg.attrs = attr;
    cfg.numAttrs = 1;
    cudaLaunchKernelEx(&cfg, k2, Fx, out);
}